// round 10
// baseline (speedup 1.0000x reference)
#include <cuda_runtime.h>
#include <cstdint>

// Problem constants
#define Hc   64
#define Wc   64
#define CC   256
#define BB   4
#define OO   256
#define KKc  9
#define HWc  4096
#define KDIM 2304            // C*KK
#define MDIM 16384           // B*H*W
#define NCH  72              // KDIM/32 K-chunks
#define CHF  4096            // floats per (128-row x 32-float) chunk tile

// Scratch (static device allocations — allowed)
__device__ float g_xt[BB * HWc * CC];                 // x in NHWC
__device__ float g_wtb[2 * NCH * CHF];                // weight, chunk-blocked+swizzled
__device__ float g_colb[(size_t)128 * NCH * CHF];     // im2col, chunk-blocked+swizzled

__device__ __forceinline__ float tf32r(float x) {
    uint32_t u;
    asm("cvt.rna.tf32.f32 %0, %1;" : "=r"(u) : "f"(x));
    return __uint_as_float(u);
}
__device__ __forceinline__ uint32_t smem_u32(const void* p) {
    uint32_t a;
    asm("{ .reg .u64 t; cvta.to.shared.u64 t, %1; cvt.u32.u64 %0, t; }" : "=r"(a) : "l"(p));
    return a;
}
__device__ __forceinline__ void mbar_init(uint32_t m, uint32_t cnt) {
    asm volatile("mbarrier.init.shared.b64 [%0], %1;" :: "r"(m), "r"(cnt) : "memory");
}
__device__ __forceinline__ void mbar_expect_tx(uint32_t m, uint32_t bytes) {
    asm volatile("mbarrier.arrive.expect_tx.shared.b64 _, [%0], %1;" :: "r"(m), "r"(bytes) : "memory");
}
__device__ __forceinline__ void mbar_wait(uint32_t m, uint32_t parity) {
    uint32_t done;
    asm volatile("{ .reg .pred p; mbarrier.try_wait.parity.shared::cta.b64 p, [%1], %2; selp.b32 %0,1,0,p; }"
        : "=r"(done) : "r"(m), "r"(parity) : "memory");
    while (!done) {
        asm volatile("{ .reg .pred p; mbarrier.try_wait.parity.shared::cta.b64 p, [%1], %2, 0x989680; selp.b32 %0,1,0,p; }"
            : "=r"(done) : "r"(m), "r"(parity) : "memory");
    }
}
__device__ __forceinline__ void bulk_g2s(uint32_t dst, const void* src, uint32_t bytes, uint32_t mbar) {
    asm volatile("cp.async.bulk.shared::cluster.global.mbarrier::complete_tx::bytes [%0], [%1], %2, [%3];"
        :: "r"(dst), "l"(src), "r"(bytes), "r"(mbar) : "memory");
}
__device__ __forceinline__ void mma_tf32(float* d, const uint32_t* a, const uint32_t* b) {
    asm volatile(
        "mma.sync.aligned.m16n8k8.row.col.f32.tf32.tf32.f32 "
        "{%0,%1,%2,%3}, {%4,%5,%6,%7}, {%8,%9}, {%0,%1,%2,%3};"
        : "+f"(d[0]), "+f"(d[1]), "+f"(d[2]), "+f"(d[3])
        : "r"(a[0]), "r"(a[1]), "r"(a[2]), "r"(a[3]), "r"(b[0]), "r"(b[1]));
}

// ---------------------------------------------------------------------------
// Kernel 1: NCHW -> NHWC transpose of x
// ---------------------------------------------------------------------------
__global__ void k_transpose(const float* __restrict__ x) {
    __shared__ float t[32][33];
    const int b  = blockIdx.z;
    const int p0 = blockIdx.x * 32;
    const int c0 = blockIdx.y * 32;
    const int tx = threadIdx.x, ty = threadIdx.y;
#pragma unroll
    for (int i = 0; i < 32; i += 8)
        t[ty + i][tx] = x[(size_t)(b * CC + c0 + ty + i) * HWc + p0 + tx];
    __syncthreads();
#pragma unroll
    for (int i = 0; i < 32; i += 8)
        g_xt[(size_t)(b * HWc + p0 + ty + i) * CC + c0 + tx] = t[tx][ty + i];
}

// ---------------------------------------------------------------------------
// Kernel 2: weight -> chunk-blocked swizzled wt: [nt][chunk][r=o&127][32f]
// float index within row: grp^(r&7) * 4 + ofs  (grp = (k&31)>>2, ofs = k&3)
// ---------------------------------------------------------------------------
__global__ void k_wt(const float* __restrict__ w) {
    const int idx = blockIdx.x * 256 + threadIdx.x;   // over OO*KDIM
    const int o  = idx / KDIM;
    const int rk = idx - o * KDIM;
    const int kk = rk >> 8;
    const int c  = rk & 255;
    const int k  = kk * 256 + c;
    const int chunk = k >> 5;
    const int fi = k & 31;
    const int grp = fi >> 2, ofs = fi & 3;
    const int r  = o & 127, nt = o >> 7;
    const int sw = grp ^ (r & 7);
    g_wtb[((size_t)(nt * NCH + chunk) * 128 + r) * 32 + sw * 4 + ofs] =
        tf32r(w[(o * CC + c) * KKc + kk]);
}

// ---------------------------------------------------------------------------
// Kernel 3: bilinear im2col -> chunk-blocked swizzled col:
// [mt = m>>7][chunk][r = m&127][32f], float4 per thread (16B group)
// ---------------------------------------------------------------------------
__global__ void k_im2col(const float* __restrict__ off,
                         const float* __restrict__ msk) {
    const int t    = threadIdx.x;
    const int sp   = blockIdx.x * 4 + (t >> 6);
    const int lane = t & 63;

    const int p   = sp & (HWc - 1);
    const int tmp = sp >> 12;
    const int kk  = tmp % KKc;
    const int b   = tmp / KKc;
    const int ho  = p >> 6, wo = p & 63;
    const int ki  = kk / 3, kj = kk - ki * 3;

    const int obase = ((b * 2 * KKc + kk * 2) * Hc + ho) * Wc + wo;
    const float dy = off[obase];
    const float dx = off[obase + Hc * Wc];
    const float mm = msk[((b * KKc + kk) * Hc + ho) * Wc + wo];

    const float py = (float)(ho - 1 + ki) + dy;
    const float px = (float)(wo - 1 + kj) + dx;
    const float y0f = floorf(py), x0f = floorf(px);
    const int   y0 = (int)y0f,    x0 = (int)x0f;
    const float wy = py - y0f,    wx = px - x0f;

    const float w00 = (1.f - wy) * (1.f - wx);
    const float w01 = (1.f - wy) * wx;
    const float w10 = wy * (1.f - wx);
    const float w11 = wy * wx;

    const int c = lane * 4;
    float4 acc = make_float4(0.f, 0.f, 0.f, 0.f);
    const float* xb = g_xt + (size_t)b * HWc * CC;

#define GATHER(yy, xx, wgt)                                                    \
    if ((unsigned)(yy) < Hc && (unsigned)(xx) < Wc) {                          \
        const float4 v = *(const float4*)&xb[(size_t)((yy) * Wc + (xx)) * CC + c]; \
        acc.x += (wgt) * v.x; acc.y += (wgt) * v.y;                            \
        acc.z += (wgt) * v.z; acc.w += (wgt) * v.w;                            \
    }
    GATHER(y0,     x0,     w00)
    GATHER(y0,     x0 + 1, w01)
    GATHER(y0 + 1, x0,     w10)
    GATHER(y0 + 1, x0 + 1, w11)
#undef GATHER

    acc.x = tf32r(acc.x * mm); acc.y = tf32r(acc.y * mm);
    acc.z = tf32r(acc.z * mm); acc.w = tf32r(acc.w * mm);

    const int m = b * HWc + p;
    const int mt = m >> 7, r = m & 127;
    const int chunk = kk * 8 + (lane >> 3);   // (kk*256 + c) >> 5
    const int grp = lane & 7;                 // ((kk*256+c)&31)>>2
    const int sw  = grp ^ (r & 7);
    *(float4*)&g_colb[((size_t)(mt * NCH + chunk) * 128 + r) * 32 + sw * 4] = acc;
}

// ---------------------------------------------------------------------------
// Kernel 4: tf32 mma.sync GEMM with TMA bulk-copy producer.
// CTA 128x128, 4 warps, warp tile 64x64, NS=3 stages (16KB A + 16KB B each),
// 2 CTAs/SM. Per chunk: 1 expect_tx + 2 cp.async.bulk (issued by thread 0).
// ---------------------------------------------------------------------------
#define NS     3
#define STGB   32768                     // bytes per stage (A+B)
#define GSMEM  (128 + NS * STGB)         // mbars + stages

__global__ __launch_bounds__(128, 2) void k_gemm_mma(float* __restrict__ out) {
    extern __shared__ float sm[];
    const uint32_t sb = smem_u32(sm);

    const int tid  = threadIdx.x;
    const int wid  = tid >> 5;
    const int lane = tid & 31;
    const int g    = lane >> 2;      // 0..7
    const int tig  = lane & 3;       // 0..3
    const int wm   = wid & 1;        // M half (64)
    const int wn   = wid >> 1;       // N half (64)
    const int nt   = blockIdx.x;     // N tile (0..1)
    const int mt   = blockIdx.y;     // M tile (0..127)
    const int bn   = nt * 128;
    const int bm   = mt * 128;

    const float* asrc = g_colb + (size_t)mt * NCH * CHF;
    const float* bsrc = g_wtb  + (size_t)nt * NCH * CHF;

    if (tid == 0) {
#pragma unroll
        for (int s = 0; s < NS; s++) mbar_init(sb + s * 8, 1);
        asm volatile("fence.proxy.async.shared::cta;" ::: "memory");
    }
    __syncthreads();

    if (tid == 0) {
#pragma unroll
        for (int s = 0; s < NS; s++) {
            mbar_expect_tx(sb + s * 8, STGB);
            bulk_g2s(sb + 128 + s * STGB,         asrc + s * CHF, 16384, sb + s * 8);
            bulk_g2s(sb + 128 + s * STGB + 16384, bsrc + s * CHF, 16384, sb + s * 8);
        }
    }

    float acc[4][8][4];
#pragma unroll
    for (int i = 0; i < 4; i++)
#pragma unroll
        for (int j = 0; j < 8; j++)
#pragma unroll
            for (int r = 0; r < 4; r++) acc[i][j][r] = 0.f;

    for (int i = 0; i < NCH; i++) {
        const int s = i % NS;
        mbar_wait(sb + s * 8, (i / NS) & 1);

        // stage floats: A at 32 + s*8192, B at +4096
        const uint32_t* A = (const uint32_t*)(sm + 32 + s * 8192);
        const uint32_t* B = A + 4096;
        const uint32_t* Ab = A + (wm * 64 + g) * 32 + tig;
        const uint32_t* Bb = B + (wn * 64 + g) * 32 + tig;

#pragma unroll
        for (int ks = 0; ks < 4; ks++) {
            const int ge = ((2 * ks) ^ g) * 4;      // even 16B-group (swizzled)
            const int go = ((2 * ks + 1) ^ g) * 4;  // odd  16B-group (swizzled)
            uint32_t af[4][4], bf[8][2];
#pragma unroll
            for (int ii = 0; ii < 4; ii++) {
                const uint32_t* pa = Ab + ii * 512;
                af[ii][0] = pa[ge];
                af[ii][1] = pa[256 + ge];
                af[ii][2] = pa[go];
                af[ii][3] = pa[256 + go];
            }
#pragma unroll
            for (int jj = 0; jj < 8; jj++) {
                const uint32_t* pb = Bb + jj * 256;
                bf[jj][0] = pb[ge];
                bf[jj][1] = pb[go];
            }
#pragma unroll
            for (int ii = 0; ii < 4; ii++)
#pragma unroll
                for (int jj = 0; jj < 8; jj++)
                    mma_tf32(acc[ii][jj], af[ii], bf[jj]);
        }

        __syncthreads();   // all warps done with stage s
        if (tid == 0 && i + NS < NCH) {
            mbar_expect_tx(sb + s * 8, STGB);
            bulk_g2s(sb + 128 + s * STGB,         asrc + (size_t)(i + NS) * CHF, 16384, sb + s * 8);
            bulk_g2s(sb + 128 + s * STGB + 16384, bsrc + (size_t)(i + NS) * CHF, 16384, sb + s * 8);
        }
    }

    // epilogue: out[b][n][p];  m = wm*64 + ii*16 + g (+8), n = wn*64 + jj*8 + tig*2 (+1)
    const int b  = bm >> 12;
    const int p0 = (bm & (HWc - 1)) + wm * 64 + g;
    float* ob = out + ((size_t)b * OO << 12) + p0;
#pragma unroll
    for (int jj = 0; jj < 8; jj++) {
        const int n = bn + wn * 64 + jj * 8 + tig * 2;
        float* o0 = ob + ((size_t)n << 12);
        float* o1 = o0 + HWc;
#pragma unroll
        for (int ii = 0; ii < 4; ii++) {
            const int mo = ii * 16;
            o0[mo]     = acc[ii][jj][0];
            o1[mo]     = acc[ii][jj][1];
            o0[mo + 8] = acc[ii][jj][2];
            o1[mo + 8] = acc[ii][jj][3];
        }
    }
}

// ---------------------------------------------------------------------------
extern "C" void kernel_launch(void* const* d_in, const int* in_sizes, int n_in,
                              void* d_out, int out_size) {
    const float* x      = (const float*)d_in[0];
    const float* offset = (const float*)d_in[1];
    const float* mask   = (const float*)d_in[2];
    const float* weight = (const float*)d_in[3];
    float* out = (float*)d_out;

    cudaFuncSetAttribute(k_gemm_mma, cudaFuncAttributeMaxDynamicSharedMemorySize, GSMEM);

    k_transpose<<<dim3(HWc / 32, CC / 32, BB), dim3(32, 8)>>>(x);
    k_wt<<<(OO * KDIM) / 256, 256>>>(weight);
    k_im2col<<<(BB * KKc * HWc) / 4, 256>>>(offset, mask);
    k_gemm_mma<<<dim3(OO / 128, MDIM / 128), 128, GSMEM>>>(out);
}

// round 11
// speedup vs baseline: 1.0002x; 1.0002x over previous
#include <cuda_runtime.h>
#include <cstdint>

// Problem constants
#define Hc   64
#define Wc   64
#define CC   256
#define BB   4
#define OO   256
#define KKc  9
#define HWc  4096
#define KDIM 2304            // C*KK
#define MDIM 16384           // B*H*W
#define NCH  72              // KDIM/32 K-chunks
#define CHF  4096            // floats per (128-row x 32-float) chunk tile

// Scratch (static device allocations — allowed)
__device__ float g_xt[BB * HWc * CC];                 // x in NHWC
__device__ float g_wtb[2 * NCH * CHF];                // weight, chunk-blocked+swizzled
__device__ float g_colb[(size_t)128 * NCH * CHF];     // im2col, chunk-blocked+swizzled

__device__ __forceinline__ float tf32r(float x) {
    uint32_t u;
    asm("cvt.rna.tf32.f32 %0, %1;" : "=r"(u) : "f"(x));
    return __uint_as_float(u);
}
__device__ __forceinline__ uint32_t smem_u32(const void* p) {
    uint32_t a;
    asm("{ .reg .u64 t; cvta.to.shared.u64 t, %1; cvt.u32.u64 %0, t; }" : "=r"(a) : "l"(p));
    return a;
}
__device__ __forceinline__ void mbar_init(uint32_t m, uint32_t cnt) {
    asm volatile("mbarrier.init.shared.b64 [%0], %1;" :: "r"(m), "r"(cnt) : "memory");
}
__device__ __forceinline__ void mbar_expect_tx(uint32_t m, uint32_t bytes) {
    asm volatile("mbarrier.arrive.expect_tx.shared.b64 _, [%0], %1;" :: "r"(m), "r"(bytes) : "memory");
}
__device__ __forceinline__ void mbar_wait(uint32_t m, uint32_t parity) {
    uint32_t done;
    asm volatile("{ .reg .pred p; mbarrier.try_wait.parity.shared::cta.b64 p, [%1], %2; selp.b32 %0,1,0,p; }"
        : "=r"(done) : "r"(m), "r"(parity) : "memory");
    while (!done) {
        asm volatile("{ .reg .pred p; mbarrier.try_wait.parity.shared::cta.b64 p, [%1], %2, 0x989680; selp.b32 %0,1,0,p; }"
            : "=r"(done) : "r"(m), "r"(parity) : "memory");
    }
}
__device__ __forceinline__ void bulk_g2s(uint32_t dst, const void* src, uint32_t bytes, uint32_t mbar) {
    asm volatile("cp.async.bulk.shared::cluster.global.mbarrier::complete_tx::bytes [%0], [%1], %2, [%3];"
        :: "r"(dst), "l"(src), "r"(bytes), "r"(mbar) : "memory");
}
__device__ __forceinline__ void mma_tf32(float* d, const uint32_t* a, const uint32_t* b) {
    asm volatile(
        "mma.sync.aligned.m16n8k8.row.col.f32.tf32.tf32.f32 "
        "{%0,%1,%2,%3}, {%4,%5,%6,%7}, {%8,%9}, {%0,%1,%2,%3};"
        : "+f"(d[0]), "+f"(d[1]), "+f"(d[2]), "+f"(d[3])
        : "r"(a[0]), "r"(a[1]), "r"(a[2]), "r"(a[3]), "r"(b[0]), "r"(b[1]));
}

// ---------------------------------------------------------------------------
// Kernel 1: NCHW -> NHWC transpose of x
// ---------------------------------------------------------------------------
__global__ void k_transpose(const float* __restrict__ x) {
    __shared__ float t[32][33];
    const int b  = blockIdx.z;
    const int p0 = blockIdx.x * 32;
    const int c0 = blockIdx.y * 32;
    const int tx = threadIdx.x, ty = threadIdx.y;
#pragma unroll
    for (int i = 0; i < 32; i += 8)
        t[ty + i][tx] = x[(size_t)(b * CC + c0 + ty + i) * HWc + p0 + tx];
    __syncthreads();
#pragma unroll
    for (int i = 0; i < 32; i += 8)
        g_xt[(size_t)(b * HWc + p0 + ty + i) * CC + c0 + tx] = t[tx][ty + i];
}

// ---------------------------------------------------------------------------
// Kernel 2: weight -> chunk-blocked swizzled wt: [nt][chunk][r=o&127][32f]
// float index within row: grp^(r&7) * 4 + ofs  (grp = (k&31)>>2, ofs = k&3)
// ---------------------------------------------------------------------------
__global__ void k_wt(const float* __restrict__ w) {
    const int idx = blockIdx.x * 256 + threadIdx.x;   // over OO*KDIM
    const int o  = idx / KDIM;
    const int rk = idx - o * KDIM;
    const int kk = rk >> 8;
    const int c  = rk & 255;
    const int k  = kk * 256 + c;
    const int chunk = k >> 5;
    const int fi = k & 31;
    const int grp = fi >> 2, ofs = fi & 3;
    const int r  = o & 127, nt = o >> 7;
    const int sw = grp ^ (r & 7);
    g_wtb[((size_t)(nt * NCH + chunk) * 128 + r) * 32 + sw * 4 + ofs] =
        tf32r(w[(o * CC + c) * KKc + kk]);
}

// ---------------------------------------------------------------------------
// Kernel 3: bilinear im2col -> chunk-blocked swizzled col:
// [mt = m>>7][chunk][r = m&127][32f], float4 per thread (16B group)
// ---------------------------------------------------------------------------
__global__ void k_im2col(const float* __restrict__ off,
                         const float* __restrict__ msk) {
    const int t    = threadIdx.x;
    const int sp   = blockIdx.x * 4 + (t >> 6);
    const int lane = t & 63;

    const int p   = sp & (HWc - 1);
    const int tmp = sp >> 12;
    const int kk  = tmp % KKc;
    const int b   = tmp / KKc;
    const int ho  = p >> 6, wo = p & 63;
    const int ki  = kk / 3, kj = kk - ki * 3;

    const int obase = ((b * 2 * KKc + kk * 2) * Hc + ho) * Wc + wo;
    const float dy = off[obase];
    const float dx = off[obase + Hc * Wc];
    const float mm = msk[((b * KKc + kk) * Hc + ho) * Wc + wo];

    const float py = (float)(ho - 1 + ki) + dy;
    const float px = (float)(wo - 1 + kj) + dx;
    const float y0f = floorf(py), x0f = floorf(px);
    const int   y0 = (int)y0f,    x0 = (int)x0f;
    const float wy = py - y0f,    wx = px - x0f;

    const float w00 = (1.f - wy) * (1.f - wx);
    const float w01 = (1.f - wy) * wx;
    const float w10 = wy * (1.f - wx);
    const float w11 = wy * wx;

    const int c = lane * 4;
    float4 acc = make_float4(0.f, 0.f, 0.f, 0.f);
    const float* xb = g_xt + (size_t)b * HWc * CC;

#define GATHER(yy, xx, wgt)                                                    \
    if ((unsigned)(yy) < Hc && (unsigned)(xx) < Wc) {                          \
        const float4 v = *(const float4*)&xb[(size_t)((yy) * Wc + (xx)) * CC + c]; \
        acc.x += (wgt) * v.x; acc.y += (wgt) * v.y;                            \
        acc.z += (wgt) * v.z; acc.w += (wgt) * v.w;                            \
    }
    GATHER(y0,     x0,     w00)
    GATHER(y0,     x0 + 1, w01)
    GATHER(y0 + 1, x0,     w10)
    GATHER(y0 + 1, x0 + 1, w11)
#undef GATHER

    acc.x = tf32r(acc.x * mm); acc.y = tf32r(acc.y * mm);
    acc.z = tf32r(acc.z * mm); acc.w = tf32r(acc.w * mm);

    const int m = b * HWc + p;
    const int mt = m >> 7, r = m & 127;
    const int chunk = kk * 8 + (lane >> 3);   // (kk*256 + c) >> 5
    const int grp = lane & 7;                 // ((kk*256+c)&31)>>2
    const int sw  = grp ^ (r & 7);
    *(float4*)&g_colb[((size_t)(mt * NCH + chunk) * 128 + r) * 32 + sw * 4] = acc;
}

// ---------------------------------------------------------------------------
// Kernel 4: tf32 mma.sync GEMM with TMA bulk-copy producer.
// CTA 128x128, 4 warps, warp tile 64x64, NS=3 stages (16KB A + 16KB B each),
// 2 CTAs/SM. Per chunk: 1 expect_tx + 2 cp.async.bulk (issued by thread 0).
// ---------------------------------------------------------------------------
#define NS     3
#define STGB   32768                     // bytes per stage (A+B)
#define GSMEM  (128 + NS * STGB)         // mbars + stages

__global__ __launch_bounds__(128, 2) void k_gemm_mma(float* __restrict__ out) {
    extern __shared__ float sm[];
    const uint32_t sb = smem_u32(sm);

    const int tid  = threadIdx.x;
    const int wid  = tid >> 5;
    const int lane = tid & 31;
    const int g    = lane >> 2;      // 0..7
    const int tig  = lane & 3;       // 0..3
    const int wm   = wid & 1;        // M half (64)
    const int wn   = wid >> 1;       // N half (64)
    const int nt   = blockIdx.x;     // N tile (0..1)
    const int mt   = blockIdx.y;     // M tile (0..127)
    const int bn   = nt * 128;
    const int bm   = mt * 128;

    const float* asrc = g_colb + (size_t)mt * NCH * CHF;
    const float* bsrc = g_wtb  + (size_t)nt * NCH * CHF;

    if (tid == 0) {
#pragma unroll
        for (int s = 0; s < NS; s++) mbar_init(sb + s * 8, 1);
        asm volatile("fence.proxy.async.shared::cta;" ::: "memory");
    }
    __syncthreads();

    if (tid == 0) {
#pragma unroll
        for (int s = 0; s < NS; s++) {
            mbar_expect_tx(sb + s * 8, STGB);
            bulk_g2s(sb + 128 + s * STGB,         asrc + s * CHF, 16384, sb + s * 8);
            bulk_g2s(sb + 128 + s * STGB + 16384, bsrc + s * CHF, 16384, sb + s * 8);
        }
    }

    float acc[4][8][4];
#pragma unroll
    for (int i = 0; i < 4; i++)
#pragma unroll
        for (int j = 0; j < 8; j++)
#pragma unroll
            for (int r = 0; r < 4; r++) acc[i][j][r] = 0.f;

    for (int i = 0; i < NCH; i++) {
        const int s = i % NS;
        mbar_wait(sb + s * 8, (i / NS) & 1);

        // stage floats: A at 32 + s*8192, B at +4096
        const uint32_t* A = (const uint32_t*)(sm + 32 + s * 8192);
        const uint32_t* B = A + 4096;
        const uint32_t* Ab = A + (wm * 64 + g) * 32 + tig;
        const uint32_t* Bb = B + (wn * 64 + g) * 32 + tig;

#pragma unroll
        for (int ks = 0; ks < 4; ks++) {
            const int ge = ((2 * ks) ^ g) * 4;      // even 16B-group (swizzled)
            const int go = ((2 * ks + 1) ^ g) * 4;  // odd  16B-group (swizzled)
            uint32_t af[4][4], bf[8][2];
#pragma unroll
            for (int ii = 0; ii < 4; ii++) {
                const uint32_t* pa = Ab + ii * 512;
                af[ii][0] = pa[ge];
                af[ii][1] = pa[256 + ge];
                af[ii][2] = pa[go];
                af[ii][3] = pa[256 + go];
            }
#pragma unroll
            for (int jj = 0; jj < 8; jj++) {
                const uint32_t* pb = Bb + jj * 256;
                bf[jj][0] = pb[ge];
                bf[jj][1] = pb[go];
            }
#pragma unroll
            for (int ii = 0; ii < 4; ii++)
#pragma unroll
                for (int jj = 0; jj < 8; jj++)
                    mma_tf32(acc[ii][jj], af[ii], bf[jj]);
        }

        __syncthreads();   // all warps done with stage s
        if (tid == 0 && i + NS < NCH) {
            mbar_expect_tx(sb + s * 8, STGB);
            bulk_g2s(sb + 128 + s * STGB,         asrc + (size_t)(i + NS) * CHF, 16384, sb + s * 8);
            bulk_g2s(sb + 128 + s * STGB + 16384, bsrc + (size_t)(i + NS) * CHF, 16384, sb + s * 8);
        }
    }

    // epilogue: out[b][n][p];  m = wm*64 + ii*16 + g (+8), n = wn*64 + jj*8 + tig*2 (+1)
    const int b  = bm >> 12;
    const int p0 = (bm & (HWc - 1)) + wm * 64 + g;
    float* ob = out + ((size_t)b * OO << 12) + p0;
#pragma unroll
    for (int jj = 0; jj < 8; jj++) {
        const int n = bn + wn * 64 + jj * 8 + tig * 2;
        float* o0 = ob + ((size_t)n << 12);
        float* o1 = o0 + HWc;
#pragma unroll
        for (int ii = 0; ii < 4; ii++) {
            const int mo = ii * 16;
            o0[mo]     = acc[ii][jj][0];
            o1[mo]     = acc[ii][jj][1];
            o0[mo + 8] = acc[ii][jj][2];
            o1[mo + 8] = acc[ii][jj][3];
        }
    }
}

// ---------------------------------------------------------------------------
extern "C" void kernel_launch(void* const* d_in, const int* in_sizes, int n_in,
                              void* d_out, int out_size) {
    const float* x      = (const float*)d_in[0];
    const float* offset = (const float*)d_in[1];
    const float* mask   = (const float*)d_in[2];
    const float* weight = (const float*)d_in[3];
    float* out = (float*)d_out;

    cudaFuncSetAttribute(k_gemm_mma, cudaFuncAttributeMaxDynamicSharedMemorySize, GSMEM);

    k_transpose<<<dim3(HWc / 32, CC / 32, BB), dim3(32, 8)>>>(x);
    k_wt<<<(OO * KDIM) / 256, 256>>>(weight);
    k_im2col<<<(BB * KKc * HWc) / 4, 256>>>(offset, mask);
    k_gemm_mma<<<dim3(OO / 128, MDIM / 128), 128, GSMEM>>>(out);
}

// round 12
// speedup vs baseline: 1.0016x; 1.0014x over previous
#include <cuda_runtime.h>
#include <cstdint>

// Problem constants
#define Hc   64
#define Wc   64
#define CC   256
#define BB   4
#define OO   256
#define KKc  9
#define HWc  4096
#define KDIM 2304            // C*KK
#define MDIM 16384           // B*H*W
#define NCH  72              // KDIM/32 K-chunks
#define CHF  4096            // floats per (128-row x 32-float) chunk tile

// Scratch (static device allocations — allowed)
__device__ float g_xt[BB * HWc * CC];                 // x in NHWC
__device__ float g_wtb[2 * NCH * CHF];                // weight, chunk-blocked+swizzled
__device__ float g_colb[(size_t)128 * NCH * CHF];     // im2col, chunk-blocked+swizzled

__device__ __forceinline__ float tf32r(float x) {
    uint32_t u;
    asm("cvt.rna.tf32.f32 %0, %1;" : "=r"(u) : "f"(x));
    return __uint_as_float(u);
}
__device__ __forceinline__ uint32_t smem_u32(const void* p) {
    uint32_t a;
    asm("{ .reg .u64 t; cvta.to.shared.u64 t, %1; cvt.u32.u64 %0, t; }" : "=r"(a) : "l"(p));
    return a;
}
__device__ __forceinline__ void mbar_init(uint32_t m, uint32_t cnt) {
    asm volatile("mbarrier.init.shared.b64 [%0], %1;" :: "r"(m), "r"(cnt) : "memory");
}
__device__ __forceinline__ void mbar_expect_tx(uint32_t m, uint32_t bytes) {
    asm volatile("mbarrier.arrive.expect_tx.shared.b64 _, [%0], %1;" :: "r"(m), "r"(bytes) : "memory");
}
__device__ __forceinline__ void mbar_wait(uint32_t m, uint32_t parity) {
    uint32_t done;
    asm volatile("{ .reg .pred p; mbarrier.try_wait.parity.shared::cta.b64 p, [%1], %2; selp.b32 %0,1,0,p; }"
        : "=r"(done) : "r"(m), "r"(parity) : "memory");
    while (!done) {
        asm volatile("{ .reg .pred p; mbarrier.try_wait.parity.shared::cta.b64 p, [%1], %2, 0x989680; selp.b32 %0,1,0,p; }"
            : "=r"(done) : "r"(m), "r"(parity) : "memory");
    }
}
__device__ __forceinline__ void bulk_g2s(uint32_t dst, const void* src, uint32_t bytes, uint32_t mbar) {
    asm volatile("cp.async.bulk.shared::cluster.global.mbarrier::complete_tx::bytes [%0], [%1], %2, [%3];"
        :: "r"(dst), "l"(src), "r"(bytes), "r"(mbar) : "memory");
}
__device__ __forceinline__ void mma_tf32(float* d, const uint32_t* a, const uint32_t* b) {
    asm volatile(
        "mma.sync.aligned.m16n8k8.row.col.f32.tf32.tf32.f32 "
        "{%0,%1,%2,%3}, {%4,%5,%6,%7}, {%8,%9}, {%0,%1,%2,%3};"
        : "+f"(d[0]), "+f"(d[1]), "+f"(d[2]), "+f"(d[3])
        : "r"(a[0]), "r"(a[1]), "r"(a[2]), "r"(a[3]), "r"(b[0]), "r"(b[1]));
}

// ---------------------------------------------------------------------------
// Kernel 1: NCHW -> NHWC transpose of x
// ---------------------------------------------------------------------------
__global__ void k_transpose(const float* __restrict__ x) {
    __shared__ float t[32][33];
    const int b  = blockIdx.z;
    const int p0 = blockIdx.x * 32;
    const int c0 = blockIdx.y * 32;
    const int tx = threadIdx.x, ty = threadIdx.y;
#pragma unroll
    for (int i = 0; i < 32; i += 8)
        t[ty + i][tx] = x[(size_t)(b * CC + c0 + ty + i) * HWc + p0 + tx];
    __syncthreads();
#pragma unroll
    for (int i = 0; i < 32; i += 8)
        g_xt[(size_t)(b * HWc + p0 + ty + i) * CC + c0 + tx] = t[tx][ty + i];
}

// ---------------------------------------------------------------------------
// Kernel 2: weight -> chunk-blocked swizzled wt: [nt][chunk][r=o&127][32f]
// float index within row: grp^(r&7) * 4 + ofs  (grp = (k&31)>>2, ofs = k&3)
// ---------------------------------------------------------------------------
__global__ void k_wt(const float* __restrict__ w) {
    const int idx = blockIdx.x * 256 + threadIdx.x;   // over OO*KDIM
    const int o  = idx / KDIM;
    const int rk = idx - o * KDIM;
    const int kk = rk >> 8;
    const int c  = rk & 255;
    const int k  = kk * 256 + c;
    const int chunk = k >> 5;
    const int fi = k & 31;
    const int grp = fi >> 2, ofs = fi & 3;
    const int r  = o & 127, nt = o >> 7;
    const int sw = grp ^ (r & 7);
    g_wtb[((size_t)(nt * NCH + chunk) * 128 + r) * 32 + sw * 4 + ofs] =
        tf32r(w[(o * CC + c) * KKc + kk]);
}

// ---------------------------------------------------------------------------
// Kernel 3: bilinear im2col -> chunk-blocked swizzled col:
// [mt = m>>7][chunk][r = m&127][32f], float4 per thread (16B group)
// ---------------------------------------------------------------------------
__global__ void k_im2col(const float* __restrict__ off,
                         const float* __restrict__ msk) {
    const int t    = threadIdx.x;
    const int sp   = blockIdx.x * 4 + (t >> 6);
    const int lane = t & 63;

    const int p   = sp & (HWc - 1);
    const int tmp = sp >> 12;
    const int kk  = tmp % KKc;
    const int b   = tmp / KKc;
    const int ho  = p >> 6, wo = p & 63;
    const int ki  = kk / 3, kj = kk - ki * 3;

    const int obase = ((b * 2 * KKc + kk * 2) * Hc + ho) * Wc + wo;
    const float dy = off[obase];
    const float dx = off[obase + Hc * Wc];
    const float mm = msk[((b * KKc + kk) * Hc + ho) * Wc + wo];

    const float py = (float)(ho - 1 + ki) + dy;
    const float px = (float)(wo - 1 + kj) + dx;
    const float y0f = floorf(py), x0f = floorf(px);
    const int   y0 = (int)y0f,    x0 = (int)x0f;
    const float wy = py - y0f,    wx = px - x0f;

    const float w00 = (1.f - wy) * (1.f - wx);
    const float w01 = (1.f - wy) * wx;
    const float w10 = wy * (1.f - wx);
    const float w11 = wy * wx;

    const int c = lane * 4;
    float4 acc = make_float4(0.f, 0.f, 0.f, 0.f);
    const float* xb = g_xt + (size_t)b * HWc * CC;

#define GATHER(yy, xx, wgt)                                                    \
    if ((unsigned)(yy) < Hc && (unsigned)(xx) < Wc) {                          \
        const float4 v = *(const float4*)&xb[(size_t)((yy) * Wc + (xx)) * CC + c]; \
        acc.x += (wgt) * v.x; acc.y += (wgt) * v.y;                            \
        acc.z += (wgt) * v.z; acc.w += (wgt) * v.w;                            \
    }
    GATHER(y0,     x0,     w00)
    GATHER(y0,     x0 + 1, w01)
    GATHER(y0 + 1, x0,     w10)
    GATHER(y0 + 1, x0 + 1, w11)
#undef GATHER

    acc.x = tf32r(acc.x * mm); acc.y = tf32r(acc.y * mm);
    acc.z = tf32r(acc.z * mm); acc.w = tf32r(acc.w * mm);

    const int m = b * HWc + p;
    const int mt = m >> 7, r = m & 127;
    const int chunk = kk * 8 + (lane >> 3);   // (kk*256 + c) >> 5
    const int grp = lane & 7;                 // ((kk*256+c)&31)>>2
    const int sw  = grp ^ (r & 7);
    *(float4*)&g_colb[((size_t)(mt * NCH + chunk) * 128 + r) * 32 + sw * 4] = acc;
}

// ---------------------------------------------------------------------------
// Kernel 4: tf32 mma.sync GEMM with TMA bulk-copy producer.
// CTA 128x128, 4 warps, warp tile 64x64, NS=3 stages (16KB A + 16KB B each),
// 2 CTAs/SM. Per chunk: 1 expect_tx + 2 cp.async.bulk (issued by thread 0).
// ---------------------------------------------------------------------------
#define NS     3
#define STGB   32768                     // bytes per stage (A+B)
#define GSMEM  (128 + NS * STGB)         // mbars + stages

__global__ __launch_bounds__(128, 2) void k_gemm_mma(float* __restrict__ out) {
    extern __shared__ float sm[];
    const uint32_t sb = smem_u32(sm);

    const int tid  = threadIdx.x;
    const int wid  = tid >> 5;
    const int lane = tid & 31;
    const int g    = lane >> 2;      // 0..7
    const int tig  = lane & 3;       // 0..3
    const int wm   = wid & 1;        // M half (64)
    const int wn   = wid >> 1;       // N half (64)
    const int nt   = blockIdx.x;     // N tile (0..1)
    const int mt   = blockIdx.y;     // M tile (0..127)
    const int bn   = nt * 128;
    const int bm   = mt * 128;

    const float* asrc = g_colb + (size_t)mt * NCH * CHF;
    const float* bsrc = g_wtb  + (size_t)nt * NCH * CHF;

    if (tid == 0) {
#pragma unroll
        for (int s = 0; s < NS; s++) mbar_init(sb + s * 8, 1);
        asm volatile("fence.proxy.async.shared::cta;" ::: "memory");
    }
    __syncthreads();

    if (tid == 0) {
#pragma unroll
        for (int s = 0; s < NS; s++) {
            mbar_expect_tx(sb + s * 8, STGB);
            bulk_g2s(sb + 128 + s * STGB,         asrc + s * CHF, 16384, sb + s * 8);
            bulk_g2s(sb + 128 + s * STGB + 16384, bsrc + s * CHF, 16384, sb + s * 8);
        }
    }

    float acc[4][8][4];
#pragma unroll
    for (int i = 0; i < 4; i++)
#pragma unroll
        for (int j = 0; j < 8; j++)
#pragma unroll
            for (int r = 0; r < 4; r++) acc[i][j][r] = 0.f;

    for (int i = 0; i < NCH; i++) {
        const int s = i % NS;
        mbar_wait(sb + s * 8, (i / NS) & 1);

        // stage floats: A at 32 + s*8192, B at +4096
        const uint32_t* A = (const uint32_t*)(sm + 32 + s * 8192);
        const uint32_t* B = A + 4096;
        const uint32_t* Ab = A + (wm * 64 + g) * 32 + tig;
        const uint32_t* Bb = B + (wn * 64 + g) * 32 + tig;

#pragma unroll
        for (int ks = 0; ks < 4; ks++) {
            const int ge = ((2 * ks) ^ g) * 4;      // even 16B-group (swizzled)
            const int go = ((2 * ks + 1) ^ g) * 4;  // odd  16B-group (swizzled)
            uint32_t af[4][4], bf[8][2];
#pragma unroll
            for (int ii = 0; ii < 4; ii++) {
                const uint32_t* pa = Ab + ii * 512;
                af[ii][0] = pa[ge];
                af[ii][1] = pa[256 + ge];
                af[ii][2] = pa[go];
                af[ii][3] = pa[256 + go];
            }
#pragma unroll
            for (int jj = 0; jj < 8; jj++) {
                const uint32_t* pb = Bb + jj * 256;
                bf[jj][0] = pb[ge];
                bf[jj][1] = pb[go];
            }
#pragma unroll
            for (int ii = 0; ii < 4; ii++)
#pragma unroll
                for (int jj = 0; jj < 8; jj++)
                    mma_tf32(acc[ii][jj], af[ii], bf[jj]);
        }

        __syncthreads();   // all warps done with stage s
        if (tid == 0 && i + NS < NCH) {
            mbar_expect_tx(sb + s * 8, STGB);
            bulk_g2s(sb + 128 + s * STGB,         asrc + (size_t)(i + NS) * CHF, 16384, sb + s * 8);
            bulk_g2s(sb + 128 + s * STGB + 16384, bsrc + (size_t)(i + NS) * CHF, 16384, sb + s * 8);
        }
    }

    // epilogue: out[b][n][p];  m = wm*64 + ii*16 + g (+8), n = wn*64 + jj*8 + tig*2 (+1)
    const int b  = bm >> 12;
    const int p0 = (bm & (HWc - 1)) + wm * 64 + g;
    float* ob = out + ((size_t)b * OO << 12) + p0;
#pragma unroll
    for (int jj = 0; jj < 8; jj++) {
        const int n = bn + wn * 64 + jj * 8 + tig * 2;
        float* o0 = ob + ((size_t)n << 12);
        float* o1 = o0 + HWc;
#pragma unroll
        for (int ii = 0; ii < 4; ii++) {
            const int mo = ii * 16;
            o0[mo]     = acc[ii][jj][0];
            o1[mo]     = acc[ii][jj][1];
            o0[mo + 8] = acc[ii][jj][2];
            o1[mo + 8] = acc[ii][jj][3];
        }
    }
}

// ---------------------------------------------------------------------------
extern "C" void kernel_launch(void* const* d_in, const int* in_sizes, int n_in,
                              void* d_out, int out_size) {
    const float* x      = (const float*)d_in[0];
    const float* offset = (const float*)d_in[1];
    const float* mask   = (const float*)d_in[2];
    const float* weight = (const float*)d_in[3];
    float* out = (float*)d_out;

    cudaFuncSetAttribute(k_gemm_mma, cudaFuncAttributeMaxDynamicSharedMemorySize, GSMEM);

    k_transpose<<<dim3(HWc / 32, CC / 32, BB), dim3(32, 8)>>>(x);
    k_wt<<<(OO * KDIM) / 256, 256>>>(weight);
    k_im2col<<<(BB * KKc * HWc) / 4, 256>>>(offset, mask);
    k_gemm_mma<<<dim3(OO / 128, MDIM / 128), 128, GSMEM>>>(out);
}

// round 13
// speedup vs baseline: 1.0045x; 1.0030x over previous
#include <cuda_runtime.h>
#include <cstdint>

// Problem constants
#define Hc   64
#define Wc   64
#define CC   256
#define BB   4
#define OO   256
#define KKc  9
#define HWc  4096
#define KDIM 2304            // C*KK
#define MDIM 16384           // B*H*W
#define NCH  72              // KDIM/32 K-chunks
#define CHF  4096            // floats per (128-row x 32-float) chunk tile

// Scratch (static device allocations — allowed)
__device__ float g_xt[BB * HWc * CC];                 // x in NHWC
__device__ float g_wtb[2 * NCH * CHF];                // weight, chunk-blocked+swizzled
__device__ float g_colb[(size_t)128 * NCH * CHF];     // im2col, chunk-blocked+swizzled

__device__ __forceinline__ float tf32r(float x) {
    uint32_t u;
    asm("cvt.rna.tf32.f32 %0, %1;" : "=r"(u) : "f"(x));
    return __uint_as_float(u);
}
__device__ __forceinline__ uint32_t smem_u32(const void* p) {
    uint32_t a;
    asm("{ .reg .u64 t; cvta.to.shared.u64 t, %1; cvt.u32.u64 %0, t; }" : "=r"(a) : "l"(p));
    return a;
}
__device__ __forceinline__ void mbar_init(uint32_t m, uint32_t cnt) {
    asm volatile("mbarrier.init.shared.b64 [%0], %1;" :: "r"(m), "r"(cnt) : "memory");
}
__device__ __forceinline__ void mbar_expect_tx(uint32_t m, uint32_t bytes) {
    asm volatile("mbarrier.arrive.expect_tx.shared.b64 _, [%0], %1;" :: "r"(m), "r"(bytes) : "memory");
}
__device__ __forceinline__ void mbar_wait(uint32_t m, uint32_t parity) {
    uint32_t done;
    asm volatile("{ .reg .pred p; mbarrier.try_wait.parity.shared::cta.b64 p, [%1], %2; selp.b32 %0,1,0,p; }"
        : "=r"(done) : "r"(m), "r"(parity) : "memory");
    while (!done) {
        asm volatile("{ .reg .pred p; mbarrier.try_wait.parity.shared::cta.b64 p, [%1], %2, 0x989680; selp.b32 %0,1,0,p; }"
            : "=r"(done) : "r"(m), "r"(parity) : "memory");
    }
}
__device__ __forceinline__ void bulk_g2s(uint32_t dst, const void* src, uint32_t bytes, uint32_t mbar) {
    asm volatile("cp.async.bulk.shared::cluster.global.mbarrier::complete_tx::bytes [%0], [%1], %2, [%3];"
        :: "r"(dst), "l"(src), "r"(bytes), "r"(mbar) : "memory");
}
__device__ __forceinline__ void mma_tf32(float* d, const uint32_t* a, const uint32_t* b) {
    asm volatile(
        "mma.sync.aligned.m16n8k8.row.col.f32.tf32.tf32.f32 "
        "{%0,%1,%2,%3}, {%4,%5,%6,%7}, {%8,%9}, {%0,%1,%2,%3};"
        : "+f"(d[0]), "+f"(d[1]), "+f"(d[2]), "+f"(d[3])
        : "r"(a[0]), "r"(a[1]), "r"(a[2]), "r"(a[3]), "r"(b[0]), "r"(b[1]));
}

// ---------------------------------------------------------------------------
// Kernel 1: NCHW -> NHWC transpose of x
// ---------------------------------------------------------------------------
__global__ void k_transpose(const float* __restrict__ x) {
    __shared__ float t[32][33];
    const int b  = blockIdx.z;
    const int p0 = blockIdx.x * 32;
    const int c0 = blockIdx.y * 32;
    const int tx = threadIdx.x, ty = threadIdx.y;
#pragma unroll
    for (int i = 0; i < 32; i += 8)
        t[ty + i][tx] = x[(size_t)(b * CC + c0 + ty + i) * HWc + p0 + tx];
    __syncthreads();
#pragma unroll
    for (int i = 0; i < 32; i += 8)
        g_xt[(size_t)(b * HWc + p0 + ty + i) * CC + c0 + tx] = t[tx][ty + i];
}

// ---------------------------------------------------------------------------
// Kernel 2: weight -> chunk-blocked swizzled wt: [nt][chunk][r=o&127][32f]
// float index within row: grp^(r&7) * 4 + ofs  (grp = (k&31)>>2, ofs = k&3)
// ---------------------------------------------------------------------------
__global__ void k_wt(const float* __restrict__ w) {
    const int idx = blockIdx.x * 256 + threadIdx.x;   // over OO*KDIM
    const int o  = idx / KDIM;
    const int rk = idx - o * KDIM;
    const int kk = rk >> 8;
    const int c  = rk & 255;
    const int k  = kk * 256 + c;
    const int chunk = k >> 5;
    const int fi = k & 31;
    const int grp = fi >> 2, ofs = fi & 3;
    const int r  = o & 127, nt = o >> 7;
    const int sw = grp ^ (r & 7);
    g_wtb[((size_t)(nt * NCH + chunk) * 128 + r) * 32 + sw * 4 + ofs] =
        tf32r(w[(o * CC + c) * KKc + kk]);
}

// ---------------------------------------------------------------------------
// Kernel 3: bilinear im2col -> chunk-blocked swizzled col:
// [mt = m>>7][chunk][r = m&127][32f], float4 per thread (16B group)
// ---------------------------------------------------------------------------
__global__ void k_im2col(const float* __restrict__ off,
                         const float* __restrict__ msk) {
    const int t    = threadIdx.x;
    const int sp   = blockIdx.x * 4 + (t >> 6);
    const int lane = t & 63;

    const int p   = sp & (HWc - 1);
    const int tmp = sp >> 12;
    const int kk  = tmp % KKc;
    const int b   = tmp / KKc;
    const int ho  = p >> 6, wo = p & 63;
    const int ki  = kk / 3, kj = kk - ki * 3;

    const int obase = ((b * 2 * KKc + kk * 2) * Hc + ho) * Wc + wo;
    const float dy = off[obase];
    const float dx = off[obase + Hc * Wc];
    const float mm = msk[((b * KKc + kk) * Hc + ho) * Wc + wo];

    const float py = (float)(ho - 1 + ki) + dy;
    const float px = (float)(wo - 1 + kj) + dx;
    const float y0f = floorf(py), x0f = floorf(px);
    const int   y0 = (int)y0f,    x0 = (int)x0f;
    const float wy = py - y0f,    wx = px - x0f;

    const float w00 = (1.f - wy) * (1.f - wx);
    const float w01 = (1.f - wy) * wx;
    const float w10 = wy * (1.f - wx);
    const float w11 = wy * wx;

    const int c = lane * 4;
    float4 acc = make_float4(0.f, 0.f, 0.f, 0.f);
    const float* xb = g_xt + (size_t)b * HWc * CC;

#define GATHER(yy, xx, wgt)                                                    \
    if ((unsigned)(yy) < Hc && (unsigned)(xx) < Wc) {                          \
        const float4 v = *(const float4*)&xb[(size_t)((yy) * Wc + (xx)) * CC + c]; \
        acc.x += (wgt) * v.x; acc.y += (wgt) * v.y;                            \
        acc.z += (wgt) * v.z; acc.w += (wgt) * v.w;                            \
    }
    GATHER(y0,     x0,     w00)
    GATHER(y0,     x0 + 1, w01)
    GATHER(y0 + 1, x0,     w10)
    GATHER(y0 + 1, x0 + 1, w11)
#undef GATHER

    acc.x = tf32r(acc.x * mm); acc.y = tf32r(acc.y * mm);
    acc.z = tf32r(acc.z * mm); acc.w = tf32r(acc.w * mm);

    const int m = b * HWc + p;
    const int mt = m >> 7, r = m & 127;
    const int chunk = kk * 8 + (lane >> 3);   // (kk*256 + c) >> 5
    const int grp = lane & 7;                 // ((kk*256+c)&31)>>2
    const int sw  = grp ^ (r & 7);
    *(float4*)&g_colb[((size_t)(mt * NCH + chunk) * 128 + r) * 32 + sw * 4] = acc;
}

// ---------------------------------------------------------------------------
// Kernel 4: tf32 mma.sync GEMM with TMA bulk-copy producer.
// CTA 128x128, 4 warps, warp tile 64x64, NS=3 stages (16KB A + 16KB B each),
// 2 CTAs/SM. Per chunk: 1 expect_tx + 2 cp.async.bulk (issued by thread 0).
// ---------------------------------------------------------------------------
#define NS     3
#define STGB   32768                     // bytes per stage (A+B)
#define GSMEM  (128 + NS * STGB)         // mbars + stages

__global__ __launch_bounds__(128, 2) void k_gemm_mma(float* __restrict__ out) {
    extern __shared__ float sm[];
    const uint32_t sb = smem_u32(sm);

    const int tid  = threadIdx.x;
    const int wid  = tid >> 5;
    const int lane = tid & 31;
    const int g    = lane >> 2;      // 0..7
    const int tig  = lane & 3;       // 0..3
    const int wm   = wid & 1;        // M half (64)
    const int wn   = wid >> 1;       // N half (64)
    const int nt   = blockIdx.x;     // N tile (0..1)
    const int mt   = blockIdx.y;     // M tile (0..127)
    const int bn   = nt * 128;
    const int bm   = mt * 128;

    const float* asrc = g_colb + (size_t)mt * NCH * CHF;
    const float* bsrc = g_wtb  + (size_t)nt * NCH * CHF;

    if (tid == 0) {
#pragma unroll
        for (int s = 0; s < NS; s++) mbar_init(sb + s * 8, 1);
        asm volatile("fence.proxy.async.shared::cta;" ::: "memory");
    }
    __syncthreads();

    if (tid == 0) {
#pragma unroll
        for (int s = 0; s < NS; s++) {
            mbar_expect_tx(sb + s * 8, STGB);
            bulk_g2s(sb + 128 + s * STGB,         asrc + s * CHF, 16384, sb + s * 8);
            bulk_g2s(sb + 128 + s * STGB + 16384, bsrc + s * CHF, 16384, sb + s * 8);
        }
    }

    float acc[4][8][4];
#pragma unroll
    for (int i = 0; i < 4; i++)
#pragma unroll
        for (int j = 0; j < 8; j++)
#pragma unroll
            for (int r = 0; r < 4; r++) acc[i][j][r] = 0.f;

    for (int i = 0; i < NCH; i++) {
        const int s = i % NS;
        mbar_wait(sb + s * 8, (i / NS) & 1);

        // stage floats: A at 32 + s*8192, B at +4096
        const uint32_t* A = (const uint32_t*)(sm + 32 + s * 8192);
        const uint32_t* B = A + 4096;
        const uint32_t* Ab = A + (wm * 64 + g) * 32 + tig;
        const uint32_t* Bb = B + (wn * 64 + g) * 32 + tig;

#pragma unroll
        for (int ks = 0; ks < 4; ks++) {
            const int ge = ((2 * ks) ^ g) * 4;      // even 16B-group (swizzled)
            const int go = ((2 * ks + 1) ^ g) * 4;  // odd  16B-group (swizzled)
            uint32_t af[4][4], bf[8][2];
#pragma unroll
            for (int ii = 0; ii < 4; ii++) {
                const uint32_t* pa = Ab + ii * 512;
                af[ii][0] = pa[ge];
                af[ii][1] = pa[256 + ge];
                af[ii][2] = pa[go];
                af[ii][3] = pa[256 + go];
            }
#pragma unroll
            for (int jj = 0; jj < 8; jj++) {
                const uint32_t* pb = Bb + jj * 256;
                bf[jj][0] = pb[ge];
                bf[jj][1] = pb[go];
            }
#pragma unroll
            for (int ii = 0; ii < 4; ii++)
#pragma unroll
                for (int jj = 0; jj < 8; jj++)
                    mma_tf32(acc[ii][jj], af[ii], bf[jj]);
        }

        __syncthreads();   // all warps done with stage s
        if (tid == 0 && i + NS < NCH) {
            mbar_expect_tx(sb + s * 8, STGB);
            bulk_g2s(sb + 128 + s * STGB,         asrc + (size_t)(i + NS) * CHF, 16384, sb + s * 8);
            bulk_g2s(sb + 128 + s * STGB + 16384, bsrc + (size_t)(i + NS) * CHF, 16384, sb + s * 8);
        }
    }

    // epilogue: out[b][n][p];  m = wm*64 + ii*16 + g (+8), n = wn*64 + jj*8 + tig*2 (+1)
    const int b  = bm >> 12;
    const int p0 = (bm & (HWc - 1)) + wm * 64 + g;
    float* ob = out + ((size_t)b * OO << 12) + p0;
#pragma unroll
    for (int jj = 0; jj < 8; jj++) {
        const int n = bn + wn * 64 + jj * 8 + tig * 2;
        float* o0 = ob + ((size_t)n << 12);
        float* o1 = o0 + HWc;
#pragma unroll
        for (int ii = 0; ii < 4; ii++) {
            const int mo = ii * 16;
            o0[mo]     = acc[ii][jj][0];
            o1[mo]     = acc[ii][jj][1];
            o0[mo + 8] = acc[ii][jj][2];
            o1[mo + 8] = acc[ii][jj][3];
        }
    }
}

// ---------------------------------------------------------------------------
extern "C" void kernel_launch(void* const* d_in, const int* in_sizes, int n_in,
                              void* d_out, int out_size) {
    const float* x      = (const float*)d_in[0];
    const float* offset = (const float*)d_in[1];
    const float* mask   = (const float*)d_in[2];
    const float* weight = (const float*)d_in[3];
    float* out = (float*)d_out;

    cudaFuncSetAttribute(k_gemm_mma, cudaFuncAttributeMaxDynamicSharedMemorySize, GSMEM);

    k_transpose<<<dim3(HWc / 32, CC / 32, BB), dim3(32, 8)>>>(x);
    k_wt<<<(OO * KDIM) / 256, 256>>>(weight);
    k_im2col<<<(BB * KKc * HWc) / 4, 256>>>(offset, mask);
    k_gemm_mma<<<dim3(OO / 128, MDIM / 128), 128, GSMEM>>>(out);
}